// round 16
// baseline (speedup 1.0000x reference)
#include <cuda_runtime.h>
#include <cstdint>
#include <cstddef>
#include <math.h>

// Problem constants (fixed by the reference: B=8, N=4096, NITER=4)
constexpr int B = 8;
constexpr int N = 4096;
constexpr int NITER = 4;
constexpr int BN = B * N;
constexpr int NPAIR = BN / 2;        // 16384 batch-pairs per plane

constexpr int NCHUNK = 64;           // chunks over b (P rows)
constexpr int CB = N / NCHUNK;       // 64 rows per chunk
constexpr int TILE_A = 512;          // cols per block
constexpr int NTILE = N / TILE_A;    // 8
constexpr int BLOCK_T = 128;
constexpr int NBLK = NTILE * NCHUNK; // 512 blocks, all co-resident

// Static scratch (no allocations allowed)
__device__ unsigned g_partb[NITER][(size_t)NCHUNK * NPAIR]; // 4 round-buffers x 4MB bf16x2
__device__ unsigned short g_Pb[(size_t)N * N];              // 32 MB bf16 P
__device__ unsigned g_cnt[NTILE];                           // per-tile monotonic arrivals
__device__ unsigned g_done;                                 // end-of-launch cleanup

using ull = unsigned long long;

__device__ __forceinline__ ull pk2(float x) {
    ull r; asm("mov.b64 %0, {%1, %1};" : "=l"(r) : "f"(x)); return r;
}
__device__ __forceinline__ ull pk2u(unsigned w) {
    ull r; asm("mov.b64 %0, {%1, %1};" : "=l"(r) : "r"(w)); return r;
}
__device__ __forceinline__ ull packf2(float lo, float hi) {
    ull r; asm("mov.b64 %0, {%1, %2};" : "=l"(r) : "f"(lo), "f"(hi)); return r;
}
__device__ __forceinline__ ull fma2(ull a, ull b, ull c) {
    ull d; asm("fma.rn.f32x2 %0, %1, %2, %3;" : "=l"(d) : "l"(a), "l"(b), "l"(c)); return d;
}
__device__ __forceinline__ unsigned cvt_pair_bf16(ull v) {
    float lo, hi;
    asm("mov.b64 {%0, %1}, %2;" : "=f"(lo), "=f"(hi) : "l"(v));
    unsigned r;
    asm("cvt.rn.bf16x2.f32 %0, %1, %2;" : "=r"(r) : "f"(hi), "f"(lo));
    return r;
}
__device__ __forceinline__ float bflo(unsigned w) { return __uint_as_float(__byte_perm(w, 0, 0x1044)); }
__device__ __forceinline__ float bfhi(unsigned w) { return __uint_as_float(__byte_perm(w, 0, 0x3244)); }

// Combine round-(t-1) partials into this block's pred chunk (smem), then clamp.
// Warp p handles batch pair p; lane handles cols {lane, lane+32} of chunk c.
__device__ __forceinline__ void combine_chunk(
    int t, int c, int p, int lane, int tid, ull* s_p2, float* s_f,
    const int* s_sdb, const int* s_sdn, int nseeds, int b0)
{
    const unsigned* __restrict__ pb =
        g_partb[t - 1] + (size_t)p * N + c * CB + lane;
    float lo0 = 0.f, hi0 = 0.f, lo1 = 0.f, hi1 = 0.f;
#pragma unroll 4
    for (int pl = 0; pl < NCHUNK; pl++) {
        unsigned w0 = __ldcg(pb + (size_t)pl * NPAIR);
        unsigned w1 = __ldcg(pb + (size_t)pl * NPAIR + 32);
        lo0 += bflo(w0); hi0 += bfhi(w0);
        lo1 += bflo(w1); hi1 += bfhi(w1);
    }
    float v00 = 1.0f - __expf(-lo0);
    float v01 = 1.0f - __expf(-hi0);
    float v10 = 1.0f - __expf(-lo1);
    float v11 = 1.0f - __expf(-hi1);
    s_p2[lane * 4 + p] = packf2(v00, v01);
    s_p2[(lane + 32) * 4 + p] = packf2(v10, v11);
    __syncthreads();
    if (tid < nseeds) {
        int lb = s_sdn[tid] - b0;
        if (lb >= 0 && lb < CB) s_f[lb * 8 + s_sdb[tid]] = 1.0f;
    }
    __syncthreads();
}

// Single persistent launch: all NITER rounds via point-to-point tile flags.
// Block (x = tile, c = chunk): round t computes partial sums
//   S_t[c][pair, a] over rows [c*64, c*64+64) for cols [x*512, (x+1)*512)
// using pred chunk c, which it recombines itself from round t-1 partials.
__global__ void __launch_bounds__(BLOCK_T, 6) prop_all(
    const float* __restrict__ P, const float* __restrict__ pred0,
    const int2* __restrict__ seed, int nseeds, float* __restrict__ out)
{
    __shared__ ull s_p2[CB * 4];        // pred chunk as f32x2 batch pairs (2 KB)
    __shared__ int s_sdb[128], s_sdn[128];
    float* s_f = reinterpret_cast<float*>(s_p2);

    const int tid = threadIdx.x;
    const int x = blockIdx.x;           // tile 0..7
    const int c = blockIdx.y;           // chunk 0..63
    const int b0 = c * CB;
    const int a0 = x * TILE_A + tid * 4;
    const int p = tid >> 5;             // warp id = batch pair (combine)
    const int lane = tid & 31;

    if (tid < nseeds) { int2 s = seed[tid]; s_sdb[tid] = s.x; s_sdn[tid] = s.y; }

#pragma unroll 1
    for (int t = 0; t < NITER; t++) {
        // ---- acquire pred chunk into smem ----
        if (t == 0) {
#pragma unroll
            for (int j = 0; j < (CB * B) / BLOCK_T; j++) {   // 4 per thread
                int idx = j * BLOCK_T + tid;
                int i = idx >> 6;           // batch
                int b = idx & (CB - 1);     // local row
                s_f[b * 8 + i] = pred0[i * N + b0 + b];
            }
            __syncthreads();
        } else {
            if (tid == 0) {
                unsigned tgt = 64u * (unsigned)t;
                while (*(volatile unsigned*)&g_cnt[c >> 3] < tgt) __nanosleep(64);
            }
            __syncthreads();
            combine_chunk(t, c, p, lane, tid, s_p2, s_f, s_sdb, s_sdn, nseeds, b0);
        }

        // ---- compute partials for this (tile, chunk) ----
        ull acc[4][4];
#pragma unroll
        for (int ai = 0; ai < 4; ai++)
#pragma unroll
            for (int pp = 0; pp < 4; pp++) acc[ai][pp] = 0ULL;

        if (t == 0) {
            // fp32 P read + inline bf16 conversion (uniform: thread owns its float4s)
            const float4* __restrict__ p4 =
                reinterpret_cast<const float4*>(P + (size_t)b0 * N) + (a0 >> 2);
            uint2* __restrict__ pbout =
                reinterpret_cast<uint2*>(g_Pb + (size_t)b0 * N + a0);
#pragma unroll 2
            for (int b = 0; b < CB; b++) {
                float4 pv = __ldg(&p4[(size_t)b * (N >> 2)]);
                uint2 w;
                asm("cvt.rn.bf16x2.f32 %0, %1, %2;" : "=r"(w.x) : "f"(pv.y), "f"(pv.x));
                asm("cvt.rn.bf16x2.f32 %0, %1, %2;" : "=r"(w.y) : "f"(pv.w), "f"(pv.z));
                pbout[(size_t)b * (N >> 2)] = w;
                ull P2[4] = { pk2(pv.x), pk2(pv.y), pk2(pv.z), pk2(pv.w) };
                ull np[4];
#pragma unroll
                for (int pp = 0; pp < 4; pp++) np[pp] = s_p2[b * 4 + pp];
#pragma unroll
                for (int ai = 0; ai < 4; ai++)
#pragma unroll
                    for (int pp = 0; pp < 4; pp++)
                        acc[ai][pp] = fma2(P2[ai], np[pp], acc[ai][pp]);
            }
        } else {
            // bf16 P sub-tile (64 KB, self-written in round 0 -> L1-friendly)
            const uint2* __restrict__ pb2 =
                reinterpret_cast<const uint2*>(g_Pb + (size_t)b0 * N + a0);
#pragma unroll 4
            for (int b = 0; b < CB; b++) {
                uint2 w = __ldg(&pb2[(size_t)b * (N >> 2)]);
                ull P2[4] = { pk2u(__byte_perm(w.x, 0, 0x1044)),
                              pk2u(__byte_perm(w.x, 0, 0x3244)),
                              pk2u(__byte_perm(w.y, 0, 0x1044)),
                              pk2u(__byte_perm(w.y, 0, 0x3244)) };
                ull np[4];
#pragma unroll
                for (int pp = 0; pp < 4; pp++) np[pp] = s_p2[b * 4 + pp];
#pragma unroll
                for (int ai = 0; ai < 4; ai++)
#pragma unroll
                    for (int pp = 0; pp < 4; pp++)
                        acc[ai][pp] = fma2(P2[ai], np[pp], acc[ai][pp]);
            }
        }

        // ---- store bf16x2 partials into round-t buffer, then arrive ----
        unsigned* outc = g_partb[t] + (size_t)c * NPAIR;
#pragma unroll
        for (int pp = 0; pp < 4; pp++) {
            uint4 w;
            w.x = cvt_pair_bf16(acc[0][pp]);
            w.y = cvt_pair_bf16(acc[1][pp]);
            w.z = cvt_pair_bf16(acc[2][pp]);
            w.w = cvt_pair_bf16(acc[3][pp]);
            *reinterpret_cast<uint4*>(outc + (size_t)pp * N + a0) = w;
        }
        __threadfence();
        __syncthreads();
        if (tid == 0) atomicAdd(&g_cnt[x], 1u);
    }

    // ---- final output: designated block per chunk writes pred_NITER ----
    if (x == (c & 7)) {
        if (tid == 0) {
            unsigned tgt = 64u * (unsigned)NITER;
            while (*(volatile unsigned*)&g_cnt[c >> 3] < tgt) __nanosleep(64);
        }
        __syncthreads();
        combine_chunk(NITER, c, p, lane, tid, s_p2, s_f, s_sdb, s_sdn, nseeds, b0);
#pragma unroll
        for (int j = 0; j < 4; j++) {
            int idx = tid * 4 + j;          // 0..511
            int b = idx >> 3, i = idx & 7;
            out[i * N + b0 + b] = s_f[b * 8 + i];
        }
        __threadfence();
    }
    __syncthreads();

    // ---- cleanup for next launch / graph replay ----
    if (tid == 0) {
        unsigned old = atomicAdd(&g_done, 1u);
        if (old == (unsigned)(NBLK - 1)) {
            for (int y = 0; y < NTILE; y++) g_cnt[y] = 0;
            __threadfence();
            g_done = 0;
        }
    }
}

extern "C" void kernel_launch(void* const* d_in, const int* in_sizes, int n_in,
                              void* d_out, int out_size) {
    const float* preds = (const float*)d_in[0];      // [B, N] fp32
    const float* P = (const float*)d_in[1];          // [N, N] fp32, P[b*N + a]
    const int2* seed = (const int2*)d_in[2];         // [NSEEDS, 2] int32 (b, n)
    int nseeds = in_sizes[2] / 2;
    if (nseeds > 128) nseeds = 128;
    float* out = (float*)d_out;

    dim3 grid(NTILE, NCHUNK);   // (8, 64) = 512 blocks, all resident
    prop_all<<<grid, BLOCK_T>>>(P, preds, seed, nseeds, out);
}